// round 13
// baseline (speedup 1.0000x reference)
#include <cuda_runtime.h>
#include <cuda_fp16.h>
#include <cstdint>
#include <math.h>

#define D 128
#define G 100
#define NLAYERS 6
#define ZDIM 133
#define IND 5
#define NMAX 20000
#define EMAX 320000
#define LOG2F_ 0.6931471805599453f

extern __shared__ char dynsmem[];

// ---------------- scratch ----------------
__device__ __align__(256) float g_h [NMAX * D];
__device__ __align__(256) float g_xf[NMAX * D];
__device__ __align__(256) float g_mi[NMAX * D];

__device__ __forceinline__ float ssp_f(float x) {
    float sp = (x > 15.0f) ? x : log1pf(__expf(x));
    return sp - LOG2F_;
}

__device__ __forceinline__ uint32_t pack_half2(float lo, float hi) {
    __half2 h = __floats2half2_rn(lo, hi);
    return *reinterpret_cast<uint32_t*>(&h);
}

__device__ __forceinline__ uint32_t smem_u32(const void* p) {
    uint32_t a;
    asm("{ .reg .u64 t; cvta.to.shared.u64 t, %1; cvt.u32.u64 %0, t; }" : "=r"(a) : "l"(p));
    return a;
}

// D(16x8) += A(16x16) * B(16x8),  f16 operands, f32 accum
__device__ __forceinline__ void mma_f16(float* d, const uint32_t* a,
                                        const uint32_t* b, const float* c) {
    asm volatile(
        "mma.sync.aligned.m16n8k16.row.col.f32.f16.f16.f32 "
        "{%0,%1,%2,%3}, {%4,%5,%6,%7}, {%8,%9}, {%10,%11,%12,%13};"
        : "=f"(d[0]), "=f"(d[1]), "=f"(d[2]), "=f"(d[3])
        : "r"(a[0]), "r"(a[1]), "r"(a[2]), "r"(a[3]),
          "r"(b[0]), "r"(b[1]),
          "f"(c[0]), "f"(c[1]), "f"(c[2]), "f"(c[3]));
}

#define LDSM_X4(r, addr)                                                     \
    asm volatile("ldmatrix.sync.aligned.m8n8.x4.shared.b16 {%0,%1,%2,%3}, [%4];" \
        : "=r"((r)[0]), "=r"((r)[1]), "=r"((r)[2]), "=r"((r)[3]) : "r"(addr))

#define BARG(id)                                                             \
    asm volatile("bar.sync %0, 256;" :: "r"(id) : "memory")

// ---------------- embed ----------------
__global__ void embed_kernel(const float* __restrict__ z,
                             const float* __restrict__ w,
                             const float* __restrict__ b, int N) {
    int gid = blockIdx.x * blockDim.x + threadIdx.x;
    if (gid >= N * D) return;
    int i = gid >> 7, d = gid & 127;
    const float* zr = z + (size_t)i * ZDIM;
    float acc = b[d] + zr[IND + d];
#pragma unroll
    for (int k = 0; k < IND; k++) acc += zr[k] * w[d * IND + k];
    g_h[gid] = acc;
}

// ---------------- xf0 = h @ lin1[0]^T ; zero m_i  (layer 0 only) ----------------
__global__ void xf_kernel(const float* __restrict__ lin1, int N) {
    float* smem = reinterpret_cast<float*>(dynsmem);
    float* wt = smem;
    float* hs = wt + D * D;
    int tid = threadIdx.x;
    for (int idx = tid; idx < D * D; idx += 256) {
        int d = idx >> 7, k = idx & 127;
        wt[k * D + d] = lin1[idx];
    }
    int tx = tid & 31, ty = tid >> 5;
    int ntiles = (N + 63) >> 6;
    for (int t = blockIdx.x; t < ntiles; t += gridDim.x) {
        int r0 = t << 6;
        __syncthreads();
        for (int idx = tid; idx < 64 * D; idx += 256) {
            int r = r0 + (idx >> 7);
            hs[idx] = (r < N) ? g_h[r * D + (idx & 127)] : 0.f;
        }
        for (int idx = tid; idx < 64 * 32; idx += 256) {
            int r = r0 + (idx >> 5);
            if (r < N)
                reinterpret_cast<float4*>(g_mi)[r * 32 + (idx & 31)] =
                    make_float4(0.f, 0.f, 0.f, 0.f);
        }
        __syncthreads();
        float4 acc[8];
#pragma unroll
        for (int j = 0; j < 8; j++) acc[j] = make_float4(0.f, 0.f, 0.f, 0.f);
#pragma unroll 4
        for (int k = 0; k < D; k++) {
            float4 w = *reinterpret_cast<const float4*>(&wt[k * D + tx * 4]);
#pragma unroll
            for (int j = 0; j < 8; j++) {
                float a = hs[(ty * 8 + j) * D + k];
                acc[j].x += a * w.x; acc[j].y += a * w.y;
                acc[j].z += a * w.z; acc[j].w += a * w.w;
            }
        }
#pragma unroll
        for (int j = 0; j < 8; j++) {
            int r = r0 + ty * 8 + j;
            if (r < N)
                *reinterpret_cast<float4*>(&g_xf[r * D + tx * 4]) = acc[j];
        }
    }
}

// ---------------- fp16 mma edge kernel: 2 independent 8-warp groups ----------------
// smem byte offsets:
//   W1N 0       (128 n-rows, stride 240, K pad 100->112)     30720
//   W2N 30720   (128 n-rows, stride 272, K=128)              34816
//   B1  65536   B2 66048
//   per group g (base GB = 66560 + g*67072):
//     ATT GB+0      half[128][120] stride 240                30720
//     HW  GB+30720  half[128][136] stride 272 (H then Wf)    34816
//     SRC GB+65536  DST GB+66048  CS GB+66560   (512 each)
#define OFF_W1N 0
#define OFF_W2N 30720
#define OFF_B1  65536
#define OFF_B2  66048
#define GRP_BASE 66560
#define GRP_SIZE 67072
#define GO_ATT  0
#define GO_HW   30720
#define GO_SRC  65536
#define GO_DST  66048
#define GO_CS   66560
#define EDGE_SMEM (GRP_BASE + 2 * GRP_SIZE)
#define ETHREADS 512

__global__ __launch_bounds__(ETHREADS, 1)
void edge_kernel(const float* __restrict__ attr,
                 const int* __restrict__ eidx,
                 const float* __restrict__ elen,
                 const float* __restrict__ w1,
                 const float* __restrict__ b1,
                 const float* __restrict__ w2,
                 const float* __restrict__ b2, int E) {
    char* dyn = dynsmem;
    uint32_t sb = smem_u32(dyn);
    int tid = threadIdx.x, lane = tid & 31;
    int grp = tid >> 8;            // 0 or 1
    int gtid = tid & 255;
    int gwid = gtid >> 5;          // 0..7
    int qr = lane >> 2, qc = lane & 3;
    int wm = (gwid & 3) * 32;      // 4 row groups x 32 rows
    int wn = (gwid >> 2) * 64;     // 2 col halves x 64 cols
    int barid = grp + 1;

    char* gb = dyn + GRP_BASE + grp * GRP_SIZE;
    uint32_t gbu = sb + GRP_BASE + grp * GRP_SIZE;

    // --- stage weights fp16 (all 512 threads) ---
    for (int idx = tid; idx < 128 * 25; idx += ETHREADS) {
        int n = idx / 25, ck = idx - n * 25;
        float4 v = *reinterpret_cast<const float4*>(w1 + (size_t)n * G + ck * 4);
        uint2 u; u.x = pack_half2(v.x, v.y); u.y = pack_half2(v.z, v.w);
        *reinterpret_cast<uint2*>(dyn + OFF_W1N + n * 240 + ck * 8) = u;
    }
    if (tid < 128) {
        uint2 z = make_uint2(0u, 0u);
        char* p = dyn + OFF_W1N + tid * 240 + 200;
        reinterpret_cast<uint2*>(p)[0] = z;
        reinterpret_cast<uint2*>(p)[1] = z;
        reinterpret_cast<uint2*>(p)[2] = z;
    }
    for (int idx = tid; idx < 128 * 32; idx += ETHREADS) {
        int n = idx >> 5, ck = idx & 31;
        float4 v = *reinterpret_cast<const float4*>(w2 + (size_t)n * D + ck * 4);
        uint2 u; u.x = pack_half2(v.x, v.y); u.y = pack_half2(v.z, v.w);
        *reinterpret_cast<uint2*>(dyn + OFF_W2N + n * 272 + ck * 8) = u;
    }
    if (tid < 128) {
        reinterpret_cast<float*>(dyn + OFF_B1)[tid] = b1[tid];
        reinterpret_cast<float*>(dyn + OFF_B2)[tid] = b2[tid];
    }
    __syncthreads();   // last block-wide sync; groups diverge below

    const float* b1s = reinterpret_cast<const float*>(dyn + OFF_B1);
    const float* b2s = reinterpret_cast<const float*>(dyn + OFF_B2);
    const int* srcs = reinterpret_cast<const int*>(gb + GO_SRC);
    const int* dsts = reinterpret_cast<const int*>(gb + GO_DST);
    const float* cs = reinterpret_cast<const float*>(gb + GO_CS);

    int ntiles = (E + 127) >> 7;
    int stride = (int)gridDim.x * 2;

    for (int t = (int)blockIdx.x * 2 + grp; t < ntiles; t += stride) {
        int e0 = t << 7;

        // stage attr tile (fp16) + meta  (256 threads of this group)
        for (int idx = gtid; idx < 128 * 25; idx += 256) {
            int r = idx / 25, ck = idx - r * 25;
            int e = e0 + r;
            float4 v = make_float4(0.f, 0.f, 0.f, 0.f);
            if (e < E)
                v = *reinterpret_cast<const float4*>(attr + (size_t)e * G + ck * 4);
            uint2 u; u.x = pack_half2(v.x, v.y); u.y = pack_half2(v.z, v.w);
            *reinterpret_cast<uint2*>(gb + GO_ATT + r * 240 + ck * 8) = u;
        }
        if (gtid < 128) {
            uint2 z = make_uint2(0u, 0u);
            char* p = gb + GO_ATT + gtid * 240 + 200;
            reinterpret_cast<uint2*>(p)[0] = z;
            reinterpret_cast<uint2*>(p)[1] = z;
            reinterpret_cast<uint2*>(p)[2] = z;
            int e = e0 + gtid;
            int s = 0, d = 0; float c = 0.f;
            if (e < E) {
                s = eidx[e]; d = eidx[E + e];
                c = (elen[e] <= 10.0f) ? 1.0f : 0.0f;
            }
            reinterpret_cast<int*>(gb + GO_SRC)[gtid] = s;
            reinterpret_cast<int*>(gb + GO_DST)[gtid] = d;
            reinterpret_cast<float*>(gb + GO_CS)[gtid] = c;
        }
        BARG(barid);

        float acc[2][8][4];
#pragma unroll
        for (int mt = 0; mt < 2; mt++)
#pragma unroll
            for (int nt = 0; nt < 8; nt++)
#pragma unroll
                for (int i = 0; i < 4; i++) acc[mt][nt][i] = 0.f;

        // GEMM1: C1 = attr @ W1^T  (K = 112)
#pragma unroll
        for (int ks = 0; ks < 7; ks++) {
            int k0h = ks * 16;
            uint32_t af[2][4], bf[4][4];
#pragma unroll
            for (int mt = 0; mt < 2; mt++)
                LDSM_X4(af[mt], gbu + GO_ATT +
                    (wm + mt * 16 + (lane & 15)) * 240 +
                    (k0h + ((lane >> 4) << 3)) * 2);
#pragma unroll
            for (int p = 0; p < 4; p++)
                LDSM_X4(bf[p], sb + OFF_W1N +
                    (wn + p * 16 + ((lane >> 4) << 3) + (lane & 7)) * 240 +
                    (k0h + (((lane >> 3) & 1) << 3)) * 2);
#pragma unroll
            for (int mt = 0; mt < 2; mt++)
#pragma unroll
                for (int nt = 0; nt < 8; nt++)
                    mma_f16(acc[mt][nt], af[mt], &bf[nt >> 1][(nt & 1) * 2], acc[mt][nt]);
        }

        // H = fp16(ssp(C1 + b1)) -> HW
#pragma unroll
        for (int mt = 0; mt < 2; mt++) {
            int row = wm + mt * 16 + qr;
#pragma unroll
            for (int nt = 0; nt < 8; nt++) {
                int col = wn + nt * 8 + qc * 2;
                float bb0 = b1s[col], bb1 = b1s[col + 1];
                *reinterpret_cast<uint32_t*>(gb + GO_HW + row * 272 + col * 2) =
                    pack_half2(ssp_f(acc[mt][nt][0] + bb0), ssp_f(acc[mt][nt][1] + bb1));
                *reinterpret_cast<uint32_t*>(gb + GO_HW + (row + 8) * 272 + col * 2) =
                    pack_half2(ssp_f(acc[mt][nt][2] + bb0), ssp_f(acc[mt][nt][3] + bb1));
            }
        }
        BARG(barid);

#pragma unroll
        for (int mt = 0; mt < 2; mt++)
#pragma unroll
            for (int nt = 0; nt < 8; nt++)
#pragma unroll
                for (int i = 0; i < 4; i++) acc[mt][nt][i] = 0.f;

        // GEMM2: C2 = H @ W2^T  (K = 128)
#pragma unroll
        for (int ks = 0; ks < 8; ks++) {
            int k0h = ks * 16;
            uint32_t af[2][4], bf[4][4];
#pragma unroll
            for (int mt = 0; mt < 2; mt++)
                LDSM_X4(af[mt], gbu + GO_HW +
                    (wm + mt * 16 + (lane & 15)) * 272 +
                    (k0h + ((lane >> 4) << 3)) * 2);
#pragma unroll
            for (int p = 0; p < 4; p++)
                LDSM_X4(bf[p], sb + OFF_W2N +
                    (wn + p * 16 + ((lane >> 4) << 3) + (lane & 7)) * 272 +
                    (k0h + (((lane >> 3) & 1) << 3)) * 2);
#pragma unroll
            for (int mt = 0; mt < 2; mt++)
#pragma unroll
                for (int nt = 0; nt < 8; nt++)
                    mma_f16(acc[mt][nt], af[mt], &bf[nt >> 1][(nt & 1) * 2], acc[mt][nt]);
        }
        BARG(barid);   // all H reads done

        // Wf = fp16((C2 + b2) * C) -> HW (overwrite H)
#pragma unroll
        for (int mt = 0; mt < 2; mt++) {
            int row = wm + mt * 16 + qr;
            float c0 = cs[row], c1 = cs[row + 8];
#pragma unroll
            for (int nt = 0; nt < 8; nt++) {
                int col = wn + nt * 8 + qc * 2;
                float bb0 = b2s[col], bb1 = b2s[col + 1];
                *reinterpret_cast<uint32_t*>(gb + GO_HW + row * 272 + col * 2) =
                    pack_half2((acc[mt][nt][0] + bb0) * c0, (acc[mt][nt][1] + bb1) * c0);
                *reinterpret_cast<uint32_t*>(gb + GO_HW + (row + 8) * 272 + col * 2) =
                    pack_half2((acc[mt][nt][2] + bb0) * c1, (acc[mt][nt][3] + bb1) * c1);
            }
        }
        BARG(barid);

        // epilogue: m_ij = xf[src] * Wf; red-add into m_i[dst]
        // 256 threads: 2 per row, each a 64-col half
        {
            int row = gtid >> 1, half = gtid & 1;
            int e = e0 + row;
            if (e < E) {
                int src = srcs[row], dst = dsts[row];
                const float4* xp = reinterpret_cast<const float4*>(
                    g_xf + (size_t)src * D + half * 64);
                float* mp = g_mi + (size_t)dst * D + half * 64;
                const uint2* wfp = reinterpret_cast<const uint2*>(
                    gb + GO_HW + row * 272 + half * 128);
#pragma unroll
                for (int i = 0; i < 16; i++) {
                    uint2 wu = wfp[i];
                    __half2 h0 = *reinterpret_cast<__half2*>(&wu.x);
                    __half2 h1 = *reinterpret_cast<__half2*>(&wu.y);
                    float2 f0 = __half22float2(h0);
                    float2 f1 = __half22float2(h1);
                    float4 x = xp[i];
                    float rx = f0.x * x.x, ry = f0.y * x.y;
                    float rz = f1.x * x.z, rw = f1.y * x.w;
                    asm volatile("red.global.add.v4.f32 [%0], {%1,%2,%3,%4};"
                                 :: "l"(mp + i * 4), "f"(rx), "f"(ry),
                                    "f"(rz), "f"(rw) : "memory");
                }
            }
        }
        BARG(barid);   // epilogue done before next tile restages
    }
}

// ---------------- fused node kernel: update + next-layer xf, fp16 mma ----------------
#define NO_L2N  0        // lin2   [n][k] f16, stride 272
#define NO_LAN  34816    // lin_w cols 0:128
#define NO_LBN  69632    // lin_w cols 128:256
#define NO_L1N  104448   // lin1 (next layer)
#define NO_HF32 139264   // float[64][132]
#define NO_H16  173056   // half, 64 rows stride 272
#define NO_M16  190464   // half, 64 rows stride 272
#define NO_B2   207872
#define NO_BL   208384
#define NODE_SMEM 208896
#define NTHREADS 512

__global__ __launch_bounds__(NTHREADS, 1)
void node_kernel(const float* __restrict__ lin2w,
                 const float* __restrict__ lin2b,
                 const float* __restrict__ linw,
                 const float* __restrict__ linb,
                 const float* __restrict__ lin1n,
                 int N, float* __restrict__ dout, int to_dout, int do_xf) {
    char* dyn = dynsmem;
    uint32_t sb = smem_u32(dyn);
    int tid = threadIdx.x, lane = tid & 31, wid = tid >> 5;
    int qr = lane >> 2, qc = lane & 3;
    int wm = (wid & 3) * 16;   // 4 row groups x 16 rows
    int wn = (wid >> 2) * 32;  // 4 col groups x 32 cols

    float* outp = to_dout ? dout : g_h;

    for (int idx = tid; idx < 128 * 32; idx += NTHREADS) {
        int n = idx >> 5, ck = idx & 31;
        float4 v = *reinterpret_cast<const float4*>(lin2w + n * D + ck * 4);
        uint2 u; u.x = pack_half2(v.x, v.y); u.y = pack_half2(v.z, v.w);
        *reinterpret_cast<uint2*>(dyn + NO_L2N + n * 272 + ck * 8) = u;
    }
    for (int idx = tid; idx < 128 * 64; idx += NTHREADS) {
        int d_ = idx >> 6, c4 = idx & 63;
        float4 v = *reinterpret_cast<const float4*>(linw + d_ * 2 * D + c4 * 4);
        uint2 u; u.x = pack_half2(v.x, v.y); u.y = pack_half2(v.z, v.w);
        if (c4 < 32)
            *reinterpret_cast<uint2*>(dyn + NO_LAN + d_ * 272 + c4 * 8) = u;
        else
            *reinterpret_cast<uint2*>(dyn + NO_LBN + d_ * 272 + (c4 - 32) * 8) = u;
    }
    if (do_xf) {
        for (int idx = tid; idx < 128 * 32; idx += NTHREADS) {
            int n = idx >> 5, ck = idx & 31;
            float4 v = *reinterpret_cast<const float4*>(lin1n + n * D + ck * 4);
            uint2 u; u.x = pack_half2(v.x, v.y); u.y = pack_half2(v.z, v.w);
            *reinterpret_cast<uint2*>(dyn + NO_L1N + n * 272 + ck * 8) = u;
        }
    }
    if (tid < 128) {
        reinterpret_cast<float*>(dyn + NO_B2)[tid] = lin2b[tid];
        reinterpret_cast<float*>(dyn + NO_BL)[tid] = linb[tid];
    }
    const float* b2s = reinterpret_cast<const float*>(dyn + NO_B2);
    const float* bls = reinterpret_cast<const float*>(dyn + NO_BL);
    float* hf = reinterpret_cast<float*>(dyn + NO_HF32);

    int ntiles = (N + 63) >> 6;
    for (int t = blockIdx.x; t < ntiles; t += gridDim.x) {
        int r0 = t << 6;
        __syncthreads();

        for (int idx = tid; idx < 64 * 32; idx += NTHREADS) {
            int r = idx >> 5, c4 = idx & 31;
            int gr = r0 + r;
            float4 hv = make_float4(0.f, 0.f, 0.f, 0.f);
            float4 mv = hv;
            if (gr < N) {
                hv = *reinterpret_cast<const float4*>(g_h + (size_t)gr * D + c4 * 4);
                mv = *reinterpret_cast<const float4*>(g_mi + (size_t)gr * D + c4 * 4);
                if (do_xf)
                    *reinterpret_cast<float4*>(g_mi + (size_t)gr * D + c4 * 4) =
                        make_float4(0.f, 0.f, 0.f, 0.f);
            }
            *reinterpret_cast<float4*>(hf + r * 132 + c4 * 4) = hv;
            uint2 uh; uh.x = pack_half2(hv.x, hv.y); uh.y = pack_half2(hv.z, hv.w);
            *reinterpret_cast<uint2*>(dyn + NO_H16 + r * 272 + c4 * 8) = uh;
            uint2 um; um.x = pack_half2(mv.x, mv.y); um.y = pack_half2(mv.z, mv.w);
            *reinterpret_cast<uint2*>(dyn + NO_M16 + r * 272 + c4 * 8) = um;
        }
        __syncthreads();

        float accm[4][4];
#pragma unroll
        for (int nt = 0; nt < 4; nt++)
#pragma unroll
            for (int i = 0; i < 4; i++) accm[nt][i] = 0.f;
#pragma unroll
        for (int ks = 0; ks < 8; ks++) {
            int k0h = ks * 16;
            uint32_t af[4], bf[2][4];
            LDSM_X4(af, sb + NO_M16 + (wm + (lane & 15)) * 272 +
                        (k0h + ((lane >> 4) << 3)) * 2);
#pragma unroll
            for (int p = 0; p < 2; p++)
                LDSM_X4(bf[p], sb + NO_L2N +
                    (wn + p * 16 + ((lane >> 4) << 3) + (lane & 7)) * 272 +
                    (k0h + (((lane >> 3) & 1) << 3)) * 2);
#pragma unroll
            for (int nt = 0; nt < 4; nt++)
                mma_f16(accm[nt], af, &bf[nt >> 1][(nt & 1) * 2], accm[nt]);
        }
        uint32_t mlo[4], mhi[4];
        int rowa = wm + qr;
#pragma unroll
        for (int nt = 0; nt < 4; nt++) {
            int col = wn + nt * 8 + qc * 2;
            float bb0 = b2s[col], bb1 = b2s[col + 1];
            mlo[nt] = pack_half2(ssp_f(accm[nt][0] + bb0), ssp_f(accm[nt][1] + bb1));
            mhi[nt] = pack_half2(ssp_f(accm[nt][2] + bb0), ssp_f(accm[nt][3] + bb1));
        }
        __syncthreads();
#pragma unroll
        for (int nt = 0; nt < 4; nt++) {
            int col = wn + nt * 8 + qc * 2;
            *reinterpret_cast<uint32_t*>(dyn + NO_M16 + rowa * 272 + col * 2) = mlo[nt];
            *reinterpret_cast<uint32_t*>(dyn + NO_M16 + (rowa + 8) * 272 + col * 2) = mhi[nt];
        }
        __syncthreads();

        float acco[4][4];
#pragma unroll
        for (int nt = 0; nt < 4; nt++)
#pragma unroll
            for (int i = 0; i < 4; i++) acco[nt][i] = 0.f;
#pragma unroll
        for (int ks = 0; ks < 8; ks++) {
            int k0h = ks * 16;
            uint32_t afh[4], afm[4], bfa[2][4], bfb[2][4];
            LDSM_X4(afh, sb + NO_H16 + (wm + (lane & 15)) * 272 +
                         (k0h + ((lane >> 4) << 3)) * 2);
            LDSM_X4(afm, sb + NO_M16 + (wm + (lane & 15)) * 272 +
                         (k0h + ((lane >> 4) << 3)) * 2);
#pragma unroll
            for (int p = 0; p < 2; p++) {
                uint32_t roff = (wn + p * 16 + ((lane >> 4) << 3) + (lane & 7)) * 272 +
                                (k0h + (((lane >> 3) & 1) << 3)) * 2;
                LDSM_X4(bfa[p], sb + NO_LAN + roff);
                LDSM_X4(bfb[p], sb + NO_LBN + roff);
            }
#pragma unroll
            for (int nt = 0; nt < 4; nt++) {
                mma_f16(acco[nt], afh, &bfa[nt >> 1][(nt & 1) * 2], acco[nt]);
                mma_f16(acco[nt], afm, &bfb[nt >> 1][(nt & 1) * 2], acco[nt]);
            }
        }
        float2 olo[4], ohi[4];
        int gr0 = r0 + rowa, gr1 = gr0 + 8;
#pragma unroll
        for (int nt = 0; nt < 4; nt++) {
            int col = wn + nt * 8 + qc * 2;
            float bb0 = bls[col], bb1 = bls[col + 1];
            float2 h0 = *reinterpret_cast<const float2*>(hf + rowa * 132 + col);
            float2 h1 = *reinterpret_cast<const float2*>(hf + (rowa + 8) * 132 + col);
            olo[nt].x = h0.x + acco[nt][0] + bb0;
            olo[nt].y = h0.y + acco[nt][1] + bb1;
            ohi[nt].x = h1.x + acco[nt][2] + bb0;
            ohi[nt].y = h1.y + acco[nt][3] + bb1;
            if (gr0 < N)
                *reinterpret_cast<float2*>(outp + (size_t)gr0 * D + col) = olo[nt];
            if (gr1 < N)
                *reinterpret_cast<float2*>(outp + (size_t)gr1 * D + col) = ohi[nt];
        }

        if (do_xf) {
            __syncthreads();
#pragma unroll
            for (int nt = 0; nt < 4; nt++) {
                int col = wn + nt * 8 + qc * 2;
                *reinterpret_cast<uint32_t*>(dyn + NO_H16 + rowa * 272 + col * 2) =
                    pack_half2(olo[nt].x, olo[nt].y);
                *reinterpret_cast<uint32_t*>(dyn + NO_H16 + (rowa + 8) * 272 + col * 2) =
                    pack_half2(ohi[nt].x, ohi[nt].y);
            }
            __syncthreads();

            float accx[4][4];
#pragma unroll
            for (int nt = 0; nt < 4; nt++)
#pragma unroll
                for (int i = 0; i < 4; i++) accx[nt][i] = 0.f;
#pragma unroll
            for (int ks = 0; ks < 8; ks++) {
                int k0h = ks * 16;
                uint32_t af[4], bf[2][4];
                LDSM_X4(af, sb + NO_H16 + (wm + (lane & 15)) * 272 +
                            (k0h + ((lane >> 4) << 3)) * 2);
#pragma unroll
                for (int p = 0; p < 2; p++)
                    LDSM_X4(bf[p], sb + NO_L1N +
                        (wn + p * 16 + ((lane >> 4) << 3) + (lane & 7)) * 272 +
                        (k0h + (((lane >> 3) & 1) << 3)) * 2);
#pragma unroll
                for (int nt = 0; nt < 4; nt++)
                    mma_f16(accx[nt], af, &bf[nt >> 1][(nt & 1) * 2], accx[nt]);
            }
#pragma unroll
            for (int nt = 0; nt < 4; nt++) {
                int col = wn + nt * 8 + qc * 2;
                float2 lo, hi;
                lo.x = accx[nt][0]; lo.y = accx[nt][1];
                hi.x = accx[nt][2]; hi.y = accx[nt][3];
                if (gr0 < N)
                    *reinterpret_cast<float2*>(g_xf + (size_t)gr0 * D + col) = lo;
                if (gr1 < N)
                    *reinterpret_cast<float2*>(g_xf + (size_t)gr1 * D + col) = hi;
            }
        }
    }
}

// ---------------- launch ----------------
extern "C" void kernel_launch(void* const* d_in, const int* in_sizes, int n_in,
                              void* d_out, int out_size) {
    const float* z    = (const float*)d_in[0];
    const int*   eidx = (const int*)d_in[1];
    const float* elen = (const float*)d_in[2];
    const float* attr = (const float*)d_in[3];
    const float* embw = (const float*)d_in[4];
    const float* embb = (const float*)d_in[5];
    const float* w1   = (const float*)d_in[6];
    const float* b1   = (const float*)d_in[7];
    const float* w2   = (const float*)d_in[8];
    const float* b2   = (const float*)d_in[9];
    const float* l1w  = (const float*)d_in[10];
    const float* l2w  = (const float*)d_in[11];
    const float* l2b  = (const float*)d_in[12];
    const float* lw   = (const float*)d_in[13];
    const float* lb   = (const float*)d_in[14];

    int N = in_sizes[0] / ZDIM;
    int E = in_sizes[2];

    const int XF_SMEM = (D * D + 64 * D) * 4;

    cudaFuncSetAttribute(xf_kernel,   cudaFuncAttributeMaxDynamicSharedMemorySize, XF_SMEM);
    cudaFuncSetAttribute(edge_kernel, cudaFuncAttributeMaxDynamicSharedMemorySize, EDGE_SMEM);
    cudaFuncSetAttribute(node_kernel, cudaFuncAttributeMaxDynamicSharedMemorySize, NODE_SMEM);

    int nsm = 148;
    cudaDeviceGetAttribute(&nsm, cudaDevAttrMultiProcessorCount, 0);

    int etiles = (E + 127) >> 7;
    int xtiles = (N + 63) >> 6;
    int ntn    = (N + 63) >> 6;
    int gx = 2 * nsm < xtiles ? 2 * nsm : xtiles;
    int gep = (etiles + 1) >> 1;
    int ge = nsm < gep ? nsm : gep;
    int gn = nsm < ntn ? nsm : ntn;

    embed_kernel<<<(N * D + 255) / 256, 256>>>(z, embw, embb, N);
    xf_kernel<<<gx, 256, XF_SMEM>>>(l1w, N);   // lin1[0] + zero m_i

    for (int l = 0; l < NLAYERS; l++) {
        edge_kernel<<<ge, ETHREADS, EDGE_SMEM>>>(attr, eidx, elen,
                                            w1 + (size_t)l * D * G, b1 + (size_t)l * D,
                                            w2 + (size_t)l * D * D, b2 + (size_t)l * D, E);
        int do_xf = (l < NLAYERS - 1);
        const float* lin1n = do_xf ? (l1w + (size_t)(l + 1) * D * D) : l1w;
        int to_dout = (l == NLAYERS - 1) ? 1 : 0;
        node_kernel<<<gn, NTHREADS, NODE_SMEM>>>(
            l2w + (size_t)l * D * D, l2b + (size_t)l * D,
            lw + (size_t)l * D * 2 * D, lb + (size_t)l * D,
            lin1n, N, (float*)d_out, to_dout, do_xf);
    }
}

// round 14
// speedup vs baseline: 1.5688x; 1.5688x over previous
#include <cuda_runtime.h>
#include <cuda_fp16.h>
#include <cstdint>
#include <math.h>

#define D 128
#define G 100
#define NLAYERS 6
#define ZDIM 133
#define IND 5
#define NMAX 20000
#define EMAX 320000
#define LOG2F_ 0.6931471805599453f

extern __shared__ char dynsmem[];

// ---------------- scratch ----------------
__device__ __align__(256) float g_h [NMAX * D];
__device__ __align__(256) float g_xf[NMAX * D];
__device__ __align__(256) float g_mi[NMAX * D];

__device__ __forceinline__ float ssp_f(float x) {
    float sp = (x > 15.0f) ? x : log1pf(__expf(x));
    return sp - LOG2F_;
}

__device__ __forceinline__ uint32_t pack_half2(float lo, float hi) {
    __half2 h = __floats2half2_rn(lo, hi);
    return *reinterpret_cast<uint32_t*>(&h);
}

__device__ __forceinline__ uint32_t smem_u32(const void* p) {
    uint32_t a;
    asm("{ .reg .u64 t; cvta.to.shared.u64 t, %1; cvt.u32.u64 %0, t; }" : "=r"(a) : "l"(p));
    return a;
}

// D(16x8) += A(16x16) * B(16x8),  f16 operands, f32 accum
__device__ __forceinline__ void mma_f16(float* d, const uint32_t* a,
                                        const uint32_t* b, const float* c) {
    asm volatile(
        "mma.sync.aligned.m16n8k16.row.col.f32.f16.f16.f32 "
        "{%0,%1,%2,%3}, {%4,%5,%6,%7}, {%8,%9}, {%10,%11,%12,%13};"
        : "=f"(d[0]), "=f"(d[1]), "=f"(d[2]), "=f"(d[3])
        : "r"(a[0]), "r"(a[1]), "r"(a[2]), "r"(a[3]),
          "r"(b[0]), "r"(b[1]),
          "f"(c[0]), "f"(c[1]), "f"(c[2]), "f"(c[3]));
}

#define LDSM_X4(r, addr)                                                     \
    asm volatile("ldmatrix.sync.aligned.m8n8.x4.shared.b16 {%0,%1,%2,%3}, [%4];" \
        : "=r"((r)[0]), "=r"((r)[1]), "=r"((r)[2]), "=r"((r)[3]) : "r"(addr))

// ---------------- embed ----------------
__global__ void embed_kernel(const float* __restrict__ z,
                             const float* __restrict__ w,
                             const float* __restrict__ b, int N) {
    int gid = blockIdx.x * blockDim.x + threadIdx.x;
    if (gid >= N * D) return;
    int i = gid >> 7, d = gid & 127;
    const float* zr = z + (size_t)i * ZDIM;
    float acc = b[d] + zr[IND + d];
#pragma unroll
    for (int k = 0; k < IND; k++) acc += zr[k] * w[d * IND + k];
    g_h[gid] = acc;
}

// ---------------- xf0 = h @ lin1[0]^T ; zero m_i  (layer 0 only) ----------------
__global__ void xf_kernel(const float* __restrict__ lin1, int N) {
    float* smem = reinterpret_cast<float*>(dynsmem);
    float* wt = smem;
    float* hs = wt + D * D;
    int tid = threadIdx.x;
    for (int idx = tid; idx < D * D; idx += 256) {
        int d = idx >> 7, k = idx & 127;
        wt[k * D + d] = lin1[idx];
    }
    int tx = tid & 31, ty = tid >> 5;
    int ntiles = (N + 63) >> 6;
    for (int t = blockIdx.x; t < ntiles; t += gridDim.x) {
        int r0 = t << 6;
        __syncthreads();
        for (int idx = tid; idx < 64 * D; idx += 256) {
            int r = r0 + (idx >> 7);
            hs[idx] = (r < N) ? g_h[r * D + (idx & 127)] : 0.f;
        }
        for (int idx = tid; idx < 64 * 32; idx += 256) {
            int r = r0 + (idx >> 5);
            if (r < N)
                reinterpret_cast<float4*>(g_mi)[r * 32 + (idx & 31)] =
                    make_float4(0.f, 0.f, 0.f, 0.f);
        }
        __syncthreads();
        float4 acc[8];
#pragma unroll
        for (int j = 0; j < 8; j++) acc[j] = make_float4(0.f, 0.f, 0.f, 0.f);
#pragma unroll 4
        for (int k = 0; k < D; k++) {
            float4 w = *reinterpret_cast<const float4*>(&wt[k * D + tx * 4]);
#pragma unroll
            for (int j = 0; j < 8; j++) {
                float a = hs[(ty * 8 + j) * D + k];
                acc[j].x += a * w.x; acc[j].y += a * w.y;
                acc[j].z += a * w.z; acc[j].w += a * w.w;
            }
        }
#pragma unroll
        for (int j = 0; j < 8; j++) {
            int r = r0 + ty * 8 + j;
            if (r < N)
                *reinterpret_cast<float4*>(&g_xf[r * D + tx * 4]) = acc[j];
        }
    }
}

// ---------------- fp16 mma edge kernel (1024 threads, 32 warps, 16x32 warp tiles) ----------------
#define OFF_AT0  0
#define OFF_AT1  30720
#define OFF_HBWF 61440
#define OFF_W1N  129024
#define OFF_W2N  159744
#define OFF_B1E  194560
#define OFF_B2E  195072
#define OFF_SRCE 195584
#define OFF_DSTE 196608
#define OFF_CSE  197632
#define EDGE_SMEM 198656
#define ETHREADS 1024

__device__ __forceinline__ void stage_tile(char* dyn, uint32_t bufoff, int slot,
                                           const float* __restrict__ attr,
                                           const int* __restrict__ eidx,
                                           const float* __restrict__ elen,
                                           int e0, int E, int tid) {
    for (int idx = tid; idx < 128 * 25; idx += ETHREADS) {
        int r = idx / 25, ck = idx - r * 25;
        int e = e0 + r;
        float4 v = make_float4(0.f, 0.f, 0.f, 0.f);
        if (e < E)
            v = *reinterpret_cast<const float4*>(attr + (size_t)e * G + ck * 4);
        uint2 u;
        u.x = pack_half2(v.x, v.y);
        u.y = pack_half2(v.z, v.w);
        *reinterpret_cast<uint2*>(dyn + bufoff + r * 240 + ck * 8) = u;
    }
    if (tid < 128) {
        uint2 z = make_uint2(0u, 0u);
        char* p = dyn + bufoff + tid * 240 + 200;
        reinterpret_cast<uint2*>(p)[0] = z;
        reinterpret_cast<uint2*>(p)[1] = z;
        reinterpret_cast<uint2*>(p)[2] = z;
        int e = e0 + tid;
        int s = 0, d = 0; float c = 0.f;
        if (e < E) {
            s = eidx[e]; d = eidx[E + e];
            c = (elen[e] <= 10.0f) ? 1.0f : 0.0f;
        }
        reinterpret_cast<int*>(dyn + OFF_SRCE + slot * 512)[tid] = s;
        reinterpret_cast<int*>(dyn + OFF_DSTE + slot * 512)[tid] = d;
        reinterpret_cast<float*>(dyn + OFF_CSE + slot * 512)[tid] = c;
    }
}

__global__ __launch_bounds__(ETHREADS, 1)
void edge_kernel(const float* __restrict__ attr,
                 const int* __restrict__ eidx,
                 const float* __restrict__ elen,
                 const float* __restrict__ w1,
                 const float* __restrict__ b1,
                 const float* __restrict__ w2,
                 const float* __restrict__ b2, int E) {
    char* dyn = dynsmem;
    uint32_t sb = smem_u32(dyn);
    int tid = threadIdx.x, lane = tid & 31, wid = tid >> 5;   // 32 warps
    int qr = lane >> 2, qc = lane & 3;
    int wm = (wid & 7) * 16;     // 8 row groups x 16 rows
    int wn = (wid >> 3) * 32;    // 4 col groups x 32 cols

    for (int idx = tid; idx < 128 * 25; idx += ETHREADS) {
        int n = idx / 25, ck = idx - n * 25;
        float4 v = *reinterpret_cast<const float4*>(w1 + (size_t)n * G + ck * 4);
        uint2 u; u.x = pack_half2(v.x, v.y); u.y = pack_half2(v.z, v.w);
        *reinterpret_cast<uint2*>(dyn + OFF_W1N + n * 240 + ck * 8) = u;
    }
    if (tid < 128) {
        uint2 z = make_uint2(0u, 0u);
        char* p = dyn + OFF_W1N + tid * 240 + 200;
        reinterpret_cast<uint2*>(p)[0] = z;
        reinterpret_cast<uint2*>(p)[1] = z;
        reinterpret_cast<uint2*>(p)[2] = z;
    }
    for (int idx = tid; idx < 128 * 32; idx += ETHREADS) {
        int n = idx >> 5, ck = idx & 31;
        float4 v = *reinterpret_cast<const float4*>(w2 + (size_t)n * D + ck * 4);
        uint2 u; u.x = pack_half2(v.x, v.y); u.y = pack_half2(v.z, v.w);
        *reinterpret_cast<uint2*>(dyn + OFF_W2N + n * 272 + ck * 8) = u;
    }
    if (tid < 128) {
        reinterpret_cast<float*>(dyn + OFF_B1E)[tid] = b1[tid];
        reinterpret_cast<float*>(dyn + OFF_B2E)[tid] = b2[tid];
    }
    const float* b1s = reinterpret_cast<const float*>(dyn + OFF_B1E);
    const float* b2s = reinterpret_cast<const float*>(dyn + OFF_B2E);

    int ntiles = (E + 127) >> 7;
    uint32_t atoff[2] = {OFF_AT0, OFF_AT1};

    if ((int)blockIdx.x < ntiles)
        stage_tile(dyn, atoff[0], 0, attr, eidx, elen, (int)blockIdx.x << 7, E, tid);
    __syncthreads();

    int b = 0;
    for (int t = blockIdx.x; t < ntiles; t += gridDim.x, b ^= 1) {
        int e0 = t << 7;
        const int* srcs = reinterpret_cast<const int*>(dyn + OFF_SRCE + b * 512);
        const int* dsts = reinterpret_cast<const int*>(dyn + OFF_DSTE + b * 512);
        const float* cs = reinterpret_cast<const float*>(dyn + OFF_CSE + b * 512);

        float acc[4][4];
#pragma unroll
        for (int nt = 0; nt < 4; nt++)
#pragma unroll
            for (int i = 0; i < 4; i++) acc[nt][i] = 0.f;

        // GEMM1: C1 = attr @ W1^T  (K = 112)
#pragma unroll
        for (int ks = 0; ks < 7; ks++) {
            int k0h = ks * 16;
            uint32_t af[4], bf[2][4];
            LDSM_X4(af, sb + atoff[b] +
                (wm + (lane & 15)) * 240 +
                (k0h + ((lane >> 4) << 3)) * 2);
#pragma unroll
            for (int p = 0; p < 2; p++)
                LDSM_X4(bf[p], sb + OFF_W1N +
                    (wn + p * 16 + ((lane >> 4) << 3) + (lane & 7)) * 240 +
                    (k0h + (((lane >> 3) & 1) << 3)) * 2);
#pragma unroll
            for (int nt = 0; nt < 4; nt++)
                mma_f16(acc[nt], af, &bf[nt >> 1][(nt & 1) * 2], acc[nt]);
        }

        // H = fp16(ssp(C1 + b1)) -> HBWF
        {
            int row = wm + qr;
#pragma unroll
            for (int nt = 0; nt < 4; nt++) {
                int col = wn + nt * 8 + qc * 2;
                float bb0 = b1s[col], bb1 = b1s[col + 1];
                *reinterpret_cast<uint32_t*>(dyn + OFF_HBWF + row * 272 + col * 2) =
                    pack_half2(ssp_f(acc[nt][0] + bb0), ssp_f(acc[nt][1] + bb1));
                *reinterpret_cast<uint32_t*>(dyn + OFF_HBWF + (row + 8) * 272 + col * 2) =
                    pack_half2(ssp_f(acc[nt][2] + bb0), ssp_f(acc[nt][3] + bb1));
            }
        }
        __syncthreads();

        // stage NEXT tile into the other buffer (overlaps GEMM2)
        if (t + (int)gridDim.x < ntiles)
            stage_tile(dyn, atoff[b ^ 1], b ^ 1, attr, eidx, elen,
                       (t + (int)gridDim.x) << 7, E, tid);

#pragma unroll
        for (int nt = 0; nt < 4; nt++)
#pragma unroll
            for (int i = 0; i < 4; i++) acc[nt][i] = 0.f;

        // GEMM2: C2 = H @ W2^T  (K = 128)
#pragma unroll
        for (int ks = 0; ks < 8; ks++) {
            int k0h = ks * 16;
            uint32_t af[4], bf[2][4];
            LDSM_X4(af, sb + OFF_HBWF +
                (wm + (lane & 15)) * 272 +
                (k0h + ((lane >> 4) << 3)) * 2);
#pragma unroll
            for (int p = 0; p < 2; p++)
                LDSM_X4(bf[p], sb + OFF_W2N +
                    (wn + p * 16 + ((lane >> 4) << 3) + (lane & 7)) * 272 +
                    (k0h + (((lane >> 3) & 1) << 3)) * 2);
#pragma unroll
            for (int nt = 0; nt < 4; nt++)
                mma_f16(acc[nt], af, &bf[nt >> 1][(nt & 1) * 2], acc[nt]);
        }
        __syncthreads();   // all H reads done (and next-tile staging complete)

        // Wf = (C2 + b2) * C -> fp32 over HBWF
        {
            float* wf = reinterpret_cast<float*>(dyn + OFF_HBWF);
            int row = wm + qr;
            float c0 = cs[row], c1 = cs[row + 8];
#pragma unroll
            for (int nt = 0; nt < 4; nt++) {
                int col = wn + nt * 8 + qc * 2;
                float bb0 = b2s[col], bb1 = b2s[col + 1];
                float2 lo, hi;
                lo.x = (acc[nt][0] + bb0) * c0;
                lo.y = (acc[nt][1] + bb1) * c0;
                hi.x = (acc[nt][2] + bb0) * c1;
                hi.y = (acc[nt][3] + bb1) * c1;
                *reinterpret_cast<float2*>(wf + row * 132 + col) = lo;
                *reinterpret_cast<float2*>(wf + (row + 8) * 132 + col) = hi;
            }
        }
        __syncthreads();

        // epilogue: m_ij = xf[src] * Wf; red-add into m_i[dst]
        // 1024 threads: 8 per row, 16 cols each
        {
            const float* wfb = reinterpret_cast<const float*>(dyn + OFF_HBWF);
            int row = tid >> 3, q = tid & 7;
            int e = e0 + row;
            if (e < E) {
                int src = srcs[row], dst = dsts[row];
                const float4* xp = reinterpret_cast<const float4*>(
                    g_xf + (size_t)src * D + q * 16);
                float* mp = g_mi + (size_t)dst * D + q * 16;
                const float* wf = wfb + row * 132 + q * 16;
#pragma unroll
                for (int i = 0; i < 4; i++) {
                    float4 w = *reinterpret_cast<const float4*>(wf + i * 4);
                    float4 x = xp[i];
                    float rx = w.x * x.x, ry = w.y * x.y;
                    float rz = w.z * x.z, rw = w.w * x.w;
                    asm volatile("red.global.add.v4.f32 [%0], {%1,%2,%3,%4};"
                                 :: "l"(mp + i * 4), "f"(rx), "f"(ry),
                                    "f"(rz), "f"(rw) : "memory");
                }
            }
        }
        __syncthreads();   // epilogue done before next iter's H store
    }
}

// ---------------- fused node kernel: update + next-layer xf, fp16 mma ----------------
#define NO_L2N  0        // lin2   [n][k] f16, stride 272
#define NO_LAN  34816    // lin_w cols 0:128
#define NO_LBN  69632    // lin_w cols 128:256
#define NO_L1N  104448   // lin1 (next layer)
#define NO_HF32 139264   // float[64][132]
#define NO_H16  173056   // half, 64 rows stride 272
#define NO_M16  190464   // half, 64 rows stride 272
#define NO_B2   207872
#define NO_BL   208384
#define NODE_SMEM 208896
#define NTHREADS 512

__global__ __launch_bounds__(NTHREADS, 1)
void node_kernel(const float* __restrict__ lin2w,
                 const float* __restrict__ lin2b,
                 const float* __restrict__ linw,
                 const float* __restrict__ linb,
                 const float* __restrict__ lin1n,
                 int N, float* __restrict__ dout, int to_dout, int do_xf) {
    char* dyn = dynsmem;
    uint32_t sb = smem_u32(dyn);
    int tid = threadIdx.x, lane = tid & 31, wid = tid >> 5;
    int qr = lane >> 2, qc = lane & 3;
    int wm = (wid & 3) * 16;   // 4 row groups x 16 rows
    int wn = (wid >> 2) * 32;  // 4 col groups x 32 cols

    float* outp = to_dout ? dout : g_h;

    for (int idx = tid; idx < 128 * 32; idx += NTHREADS) {
        int n = idx >> 5, ck = idx & 31;
        float4 v = *reinterpret_cast<const float4*>(lin2w + n * D + ck * 4);
        uint2 u; u.x = pack_half2(v.x, v.y); u.y = pack_half2(v.z, v.w);
        *reinterpret_cast<uint2*>(dyn + NO_L2N + n * 272 + ck * 8) = u;
    }
    for (int idx = tid; idx < 128 * 64; idx += NTHREADS) {
        int d_ = idx >> 6, c4 = idx & 63;
        float4 v = *reinterpret_cast<const float4*>(linw + d_ * 2 * D + c4 * 4);
        uint2 u; u.x = pack_half2(v.x, v.y); u.y = pack_half2(v.z, v.w);
        if (c4 < 32)
            *reinterpret_cast<uint2*>(dyn + NO_LAN + d_ * 272 + c4 * 8) = u;
        else
            *reinterpret_cast<uint2*>(dyn + NO_LBN + d_ * 272 + (c4 - 32) * 8) = u;
    }
    if (do_xf) {
        for (int idx = tid; idx < 128 * 32; idx += NTHREADS) {
            int n = idx >> 5, ck = idx & 31;
            float4 v = *reinterpret_cast<const float4*>(lin1n + n * D + ck * 4);
            uint2 u; u.x = pack_half2(v.x, v.y); u.y = pack_half2(v.z, v.w);
            *reinterpret_cast<uint2*>(dyn + NO_L1N + n * 272 + ck * 8) = u;
        }
    }
    if (tid < 128) {
        reinterpret_cast<float*>(dyn + NO_B2)[tid] = lin2b[tid];
        reinterpret_cast<float*>(dyn + NO_BL)[tid] = linb[tid];
    }
    const float* b2s = reinterpret_cast<const float*>(dyn + NO_B2);
    const float* bls = reinterpret_cast<const float*>(dyn + NO_BL);
    float* hf = reinterpret_cast<float*>(dyn + NO_HF32);

    int ntiles = (N + 63) >> 6;
    for (int t = blockIdx.x; t < ntiles; t += gridDim.x) {
        int r0 = t << 6;
        __syncthreads();

        for (int idx = tid; idx < 64 * 32; idx += NTHREADS) {
            int r = idx >> 5, c4 = idx & 31;
            int gr = r0 + r;
            float4 hv = make_float4(0.f, 0.f, 0.f, 0.f);
            float4 mv = hv;
            if (gr < N) {
                hv = *reinterpret_cast<const float4*>(g_h + (size_t)gr * D + c4 * 4);
                mv = *reinterpret_cast<const float4*>(g_mi + (size_t)gr * D + c4 * 4);
                if (do_xf)
                    *reinterpret_cast<float4*>(g_mi + (size_t)gr * D + c4 * 4) =
                        make_float4(0.f, 0.f, 0.f, 0.f);
            }
            *reinterpret_cast<float4*>(hf + r * 132 + c4 * 4) = hv;
            uint2 uh; uh.x = pack_half2(hv.x, hv.y); uh.y = pack_half2(hv.z, hv.w);
            *reinterpret_cast<uint2*>(dyn + NO_H16 + r * 272 + c4 * 8) = uh;
            uint2 um; um.x = pack_half2(mv.x, mv.y); um.y = pack_half2(mv.z, mv.w);
            *reinterpret_cast<uint2*>(dyn + NO_M16 + r * 272 + c4 * 8) = um;
        }
        __syncthreads();

        float accm[4][4];
#pragma unroll
        for (int nt = 0; nt < 4; nt++)
#pragma unroll
            for (int i = 0; i < 4; i++) accm[nt][i] = 0.f;
#pragma unroll
        for (int ks = 0; ks < 8; ks++) {
            int k0h = ks * 16;
            uint32_t af[4], bf[2][4];
            LDSM_X4(af, sb + NO_M16 + (wm + (lane & 15)) * 272 +
                        (k0h + ((lane >> 4) << 3)) * 2);
#pragma unroll
            for (int p = 0; p < 2; p++)
                LDSM_X4(bf[p], sb + NO_L2N +
                    (wn + p * 16 + ((lane >> 4) << 3) + (lane & 7)) * 272 +
                    (k0h + (((lane >> 3) & 1) << 3)) * 2);
#pragma unroll
            for (int nt = 0; nt < 4; nt++)
                mma_f16(accm[nt], af, &bf[nt >> 1][(nt & 1) * 2], accm[nt]);
        }
        uint32_t mlo[4], mhi[4];
        int rowa = wm + qr;
#pragma unroll
        for (int nt = 0; nt < 4; nt++) {
            int col = wn + nt * 8 + qc * 2;
            float bb0 = b2s[col], bb1 = b2s[col + 1];
            mlo[nt] = pack_half2(ssp_f(accm[nt][0] + bb0), ssp_f(accm[nt][1] + bb1));
            mhi[nt] = pack_half2(ssp_f(accm[nt][2] + bb0), ssp_f(accm[nt][3] + bb1));
        }
        __syncthreads();
#pragma unroll
        for (int nt = 0; nt < 4; nt++) {
            int col = wn + nt * 8 + qc * 2;
            *reinterpret_cast<uint32_t*>(dyn + NO_M16 + rowa * 272 + col * 2) = mlo[nt];
            *reinterpret_cast<uint32_t*>(dyn + NO_M16 + (rowa + 8) * 272 + col * 2) = mhi[nt];
        }
        __syncthreads();

        float acco[4][4];
#pragma unroll
        for (int nt = 0; nt < 4; nt++)
#pragma unroll
            for (int i = 0; i < 4; i++) acco[nt][i] = 0.f;
#pragma unroll
        for (int ks = 0; ks < 8; ks++) {
            int k0h = ks * 16;
            uint32_t afh[4], afm[4], bfa[2][4], bfb[2][4];
            LDSM_X4(afh, sb + NO_H16 + (wm + (lane & 15)) * 272 +
                         (k0h + ((lane >> 4) << 3)) * 2);
            LDSM_X4(afm, sb + NO_M16 + (wm + (lane & 15)) * 272 +
                         (k0h + ((lane >> 4) << 3)) * 2);
#pragma unroll
            for (int p = 0; p < 2; p++) {
                uint32_t roff = (wn + p * 16 + ((lane >> 4) << 3) + (lane & 7)) * 272 +
                                (k0h + (((lane >> 3) & 1) << 3)) * 2;
                LDSM_X4(bfa[p], sb + NO_LAN + roff);
                LDSM_X4(bfb[p], sb + NO_LBN + roff);
            }
#pragma unroll
            for (int nt = 0; nt < 4; nt++) {
                mma_f16(acco[nt], afh, &bfa[nt >> 1][(nt & 1) * 2], acco[nt]);
                mma_f16(acco[nt], afm, &bfb[nt >> 1][(nt & 1) * 2], acco[nt]);
            }
        }
        float2 olo[4], ohi[4];
        int gr0 = r0 + rowa, gr1 = gr0 + 8;
#pragma unroll
        for (int nt = 0; nt < 4; nt++) {
            int col = wn + nt * 8 + qc * 2;
            float bb0 = bls[col], bb1 = bls[col + 1];
            float2 h0 = *reinterpret_cast<const float2*>(hf + rowa * 132 + col);
            float2 h1 = *reinterpret_cast<const float2*>(hf + (rowa + 8) * 132 + col);
            olo[nt].x = h0.x + acco[nt][0] + bb0;
            olo[nt].y = h0.y + acco[nt][1] + bb1;
            ohi[nt].x = h1.x + acco[nt][2] + bb0;
            ohi[nt].y = h1.y + acco[nt][3] + bb1;
            if (gr0 < N)
                *reinterpret_cast<float2*>(outp + (size_t)gr0 * D + col) = olo[nt];
            if (gr1 < N)
                *reinterpret_cast<float2*>(outp + (size_t)gr1 * D + col) = ohi[nt];
        }

        if (do_xf) {
            __syncthreads();
#pragma unroll
            for (int nt = 0; nt < 4; nt++) {
                int col = wn + nt * 8 + qc * 2;
                *reinterpret_cast<uint32_t*>(dyn + NO_H16 + rowa * 272 + col * 2) =
                    pack_half2(olo[nt].x, olo[nt].y);
                *reinterpret_cast<uint32_t*>(dyn + NO_H16 + (rowa + 8) * 272 + col * 2) =
                    pack_half2(ohi[nt].x, ohi[nt].y);
            }
            __syncthreads();

            float accx[4][4];
#pragma unroll
            for (int nt = 0; nt < 4; nt++)
#pragma unroll
                for (int i = 0; i < 4; i++) accx[nt][i] = 0.f;
#pragma unroll
            for (int ks = 0; ks < 8; ks++) {
                int k0h = ks * 16;
                uint32_t af[4], bf[2][4];
                LDSM_X4(af, sb + NO_H16 + (wm + (lane & 15)) * 272 +
                            (k0h + ((lane >> 4) << 3)) * 2);
#pragma unroll
                for (int p = 0; p < 2; p++)
                    LDSM_X4(bf[p], sb + NO_L1N +
                        (wn + p * 16 + ((lane >> 4) << 3) + (lane & 7)) * 272 +
                        (k0h + (((lane >> 3) & 1) << 3)) * 2);
#pragma unroll
                for (int nt = 0; nt < 4; nt++)
                    mma_f16(accx[nt], af, &bf[nt >> 1][(nt & 1) * 2], accx[nt]);
            }
#pragma unroll
            for (int nt = 0; nt < 4; nt++) {
                int col = wn + nt * 8 + qc * 2;
                float2 lo, hi;
                lo.x = accx[nt][0]; lo.y = accx[nt][1];
                hi.x = accx[nt][2]; hi.y = accx[nt][3];
                if (gr0 < N)
                    *reinterpret_cast<float2*>(g_xf + (size_t)gr0 * D + col) = lo;
                if (gr1 < N)
                    *reinterpret_cast<float2*>(g_xf + (size_t)gr1 * D + col) = hi;
            }
        }
    }
}

// ---------------- launch ----------------
extern "C" void kernel_launch(void* const* d_in, const int* in_sizes, int n_in,
                              void* d_out, int out_size) {
    const float* z    = (const float*)d_in[0];
    const int*   eidx = (const int*)d_in[1];
    const float* elen = (const float*)d_in[2];
    const float* attr = (const float*)d_in[3];
    const float* embw = (const float*)d_in[4];
    const float* embb = (const float*)d_in[5];
    const float* w1   = (const float*)d_in[6];
    const float* b1   = (const float*)d_in[7];
    const float* w2   = (const float*)d_in[8];
    const float* b2   = (const float*)d_in[9];
    const float* l1w  = (const float*)d_in[10];
    const float* l2w  = (const float*)d_in[11];
    const float* l2b  = (const float*)d_in[12];
    const float* lw   = (const float*)d_in[13];
    const float* lb   = (const float*)d_in[14];

    int N = in_sizes[0] / ZDIM;
    int E = in_sizes[2];

    const int XF_SMEM = (D * D + 64 * D) * 4;

    cudaFuncSetAttribute(xf_kernel,   cudaFuncAttributeMaxDynamicSharedMemorySize, XF_SMEM);
    cudaFuncSetAttribute(edge_kernel, cudaFuncAttributeMaxDynamicSharedMemorySize, EDGE_SMEM);
    cudaFuncSetAttribute(node_kernel, cudaFuncAttributeMaxDynamicSharedMemorySize, NODE_SMEM);

    int nsm = 148;
    cudaDeviceGetAttribute(&nsm, cudaDevAttrMultiProcessorCount, 0);

    int etiles = (E + 127) >> 7;
    int xtiles = (N + 63) >> 6;
    int ntn    = (N + 63) >> 6;
    int gx = 2 * nsm < xtiles ? 2 * nsm : xtiles;
    int ge = nsm < etiles ? nsm : etiles;
    int gn = nsm < ntn ? nsm : ntn;

    embed_kernel<<<(N * D + 255) / 256, 256>>>(z, embw, embb, N);
    xf_kernel<<<gx, 256, XF_SMEM>>>(l1w, N);   // lin1[0] + zero m_i

    for (int l = 0; l < NLAYERS; l++) {
        edge_kernel<<<ge, ETHREADS, EDGE_SMEM>>>(attr, eidx, elen,
                                            w1 + (size_t)l * D * G, b1 + (size_t)l * D,
                                            w2 + (size_t)l * D * D, b2 + (size_t)l * D, E);
        int do_xf = (l < NLAYERS - 1);
        const float* lin1n = do_xf ? (l1w + (size_t)(l + 1) * D * D) : l1w;
        int to_dout = (l == NLAYERS - 1) ? 1 : 0;
        node_kernel<<<gn, NTHREADS, NODE_SMEM>>>(
            l2w + (size_t)l * D * D, l2b + (size_t)l * D,
            lw + (size_t)l * D * 2 * D, lb + (size_t)l * D,
            lin1n, N, (float*)d_out, to_dout, do_xf);
    }
}

// round 17
// speedup vs baseline: 1.6946x; 1.0802x over previous
#include <cuda_runtime.h>
#include <cuda_fp16.h>
#include <cstdint>
#include <math.h>

#define D 128
#define G 100
#define NLAYERS 6
#define ZDIM 133
#define IND 5
#define NMAX 20000
#define EMAX 320000
#define LOG2F_ 0.6931471805599453f

extern __shared__ char dynsmem[];

// ---------------- scratch ----------------
__device__ __align__(256) float g_h [NMAX * D];
__device__ __align__(256) float g_xf[NMAX * D];
__device__ __align__(256) float g_mi[NMAX * D];

__device__ __forceinline__ float ssp_f(float x) {
    float sp = (x > 15.0f) ? x : log1pf(__expf(x));
    return sp - LOG2F_;
}

__device__ __forceinline__ uint32_t pack_half2(float lo, float hi) {
    __half2 h = __floats2half2_rn(lo, hi);
    return *reinterpret_cast<uint32_t*>(&h);
}

__device__ __forceinline__ uint32_t smem_u32(const void* p) {
    uint32_t a;
    asm("{ .reg .u64 t; cvta.to.shared.u64 t, %1; cvt.u32.u64 %0, t; }" : "=r"(a) : "l"(p));
    return a;
}

// D(16x8) += A(16x16) * B(16x8),  f16 operands, f32 accum
__device__ __forceinline__ void mma_f16(float* d, const uint32_t* a,
                                        const uint32_t* b, const float* c) {
    asm volatile(
        "mma.sync.aligned.m16n8k16.row.col.f32.f16.f16.f32 "
        "{%0,%1,%2,%3}, {%4,%5,%6,%7}, {%8,%9}, {%10,%11,%12,%13};"
        : "=f"(d[0]), "=f"(d[1]), "=f"(d[2]), "=f"(d[3])
        : "r"(a[0]), "r"(a[1]), "r"(a[2]), "r"(a[3]),
          "r"(b[0]), "r"(b[1]),
          "f"(c[0]), "f"(c[1]), "f"(c[2]), "f"(c[3]));
}

#define LDSM_X4(r, addr)                                                     \
    asm volatile("ldmatrix.sync.aligned.m8n8.x4.shared.b16 {%0,%1,%2,%3}, [%4];" \
        : "=r"((r)[0]), "=r"((r)[1]), "=r"((r)[2]), "=r"((r)[3]) : "r"(addr))

// ---------------- embed ----------------
__global__ void embed_kernel(const float* __restrict__ z,
                             const float* __restrict__ w,
                             const float* __restrict__ b, int N) {
    int gid = blockIdx.x * blockDim.x + threadIdx.x;
    if (gid >= N * D) return;
    int i = gid >> 7, d = gid & 127;
    const float* zr = z + (size_t)i * ZDIM;
    float acc = b[d] + zr[IND + d];
#pragma unroll
    for (int k = 0; k < IND; k++) acc += zr[k] * w[d * IND + k];
    g_h[gid] = acc;
}

// ---------------- xf0 = h @ lin1[0]^T ; zero m_i  (layer 0 only) ----------------
__global__ void xf_kernel(const float* __restrict__ lin1, int N) {
    float* smem = reinterpret_cast<float*>(dynsmem);
    float* wt = smem;
    float* hs = wt + D * D;
    int tid = threadIdx.x;
    for (int idx = tid; idx < D * D; idx += 256) {
        int d = idx >> 7, k = idx & 127;
        wt[k * D + d] = lin1[idx];
    }
    int tx = tid & 31, ty = tid >> 5;
    int ntiles = (N + 63) >> 6;
    for (int t = blockIdx.x; t < ntiles; t += gridDim.x) {
        int r0 = t << 6;
        __syncthreads();
        for (int idx = tid; idx < 64 * D; idx += 256) {
            int r = r0 + (idx >> 7);
            hs[idx] = (r < N) ? g_h[r * D + (idx & 127)] : 0.f;
        }
        for (int idx = tid; idx < 64 * 32; idx += 256) {
            int r = r0 + (idx >> 5);
            if (r < N)
                reinterpret_cast<float4*>(g_mi)[r * 32 + (idx & 31)] =
                    make_float4(0.f, 0.f, 0.f, 0.f);
        }
        __syncthreads();
        float4 acc[8];
#pragma unroll
        for (int j = 0; j < 8; j++) acc[j] = make_float4(0.f, 0.f, 0.f, 0.f);
#pragma unroll 4
        for (int k = 0; k < D; k++) {
            float4 w = *reinterpret_cast<const float4*>(&wt[k * D + tx * 4]);
#pragma unroll
            for (int j = 0; j < 8; j++) {
                float a = hs[(ty * 8 + j) * D + k];
                acc[j].x += a * w.x; acc[j].y += a * w.y;
                acc[j].z += a * w.z; acc[j].w += a * w.w;
            }
        }
#pragma unroll
        for (int j = 0; j < 8; j++) {
            int r = r0 + ty * 8 + j;
            if (r < N)
                *reinterpret_cast<float4*>(&g_xf[r * D + tx * 4]) = acc[j];
        }
    }
}

// ---------------- fp16 mma edge kernel (1024 threads, 32 warps, 16x32 warp tiles) ----------------
#define OFF_AT0  0
#define OFF_AT1  30720
#define OFF_HBWF 61440
#define OFF_W1N  129024
#define OFF_W2N  159744
#define OFF_B1E  194560
#define OFF_B2E  195072
#define OFF_SRCE 195584
#define OFF_DSTE 196608
#define OFF_CSE  197632
#define EDGE_SMEM 198656
#define ETHREADS 1024

__device__ __forceinline__ void stage_tile(char* dyn, uint32_t bufoff, int slot,
                                           const float* __restrict__ attr,
                                           const int* __restrict__ eidx,
                                           const float* __restrict__ elen,
                                           int e0, int E, int tid) {
    for (int idx = tid; idx < 128 * 25; idx += ETHREADS) {
        int r = idx / 25, ck = idx - r * 25;
        int e = e0 + r;
        float4 v = make_float4(0.f, 0.f, 0.f, 0.f);
        if (e < E)
            v = *reinterpret_cast<const float4*>(attr + (size_t)e * G + ck * 4);
        uint2 u;
        u.x = pack_half2(v.x, v.y);
        u.y = pack_half2(v.z, v.w);
        *reinterpret_cast<uint2*>(dyn + bufoff + r * 240 + ck * 8) = u;
    }
    if (tid < 128) {
        uint2 z = make_uint2(0u, 0u);
        char* p = dyn + bufoff + tid * 240 + 200;
        reinterpret_cast<uint2*>(p)[0] = z;
        reinterpret_cast<uint2*>(p)[1] = z;
        reinterpret_cast<uint2*>(p)[2] = z;
        int e = e0 + tid;
        int s = 0, d = 0; float c = 0.f;
        if (e < E) {
            s = eidx[e]; d = eidx[E + e];
            c = (elen[e] <= 10.0f) ? 1.0f : 0.0f;
        }
        reinterpret_cast<int*>(dyn + OFF_SRCE + slot * 512)[tid] = s;
        reinterpret_cast<int*>(dyn + OFF_DSTE + slot * 512)[tid] = d;
        reinterpret_cast<float*>(dyn + OFF_CSE + slot * 512)[tid] = c;
    }
}

__global__ __launch_bounds__(ETHREADS, 1)
void edge_kernel(const float* __restrict__ attr,
                 const int* __restrict__ eidx,
                 const float* __restrict__ elen,
                 const float* __restrict__ w1,
                 const float* __restrict__ b1,
                 const float* __restrict__ w2,
                 const float* __restrict__ b2, int E) {
    char* dyn = dynsmem;
    uint32_t sb = smem_u32(dyn);
    int tid = threadIdx.x, lane = tid & 31, wid = tid >> 5;   // 32 warps
    int qr = lane >> 2, qc = lane & 3;
    int wm = (wid & 7) * 16;     // 8 row groups x 16 rows
    int wn = (wid >> 3) * 32;    // 4 col groups x 32 cols

    for (int idx = tid; idx < 128 * 25; idx += ETHREADS) {
        int n = idx / 25, ck = idx - n * 25;
        float4 v = *reinterpret_cast<const float4*>(w1 + (size_t)n * G + ck * 4);
        uint2 u; u.x = pack_half2(v.x, v.y); u.y = pack_half2(v.z, v.w);
        *reinterpret_cast<uint2*>(dyn + OFF_W1N + n * 240 + ck * 8) = u;
    }
    if (tid < 128) {
        uint2 z = make_uint2(0u, 0u);
        char* p = dyn + OFF_W1N + tid * 240 + 200;
        reinterpret_cast<uint2*>(p)[0] = z;
        reinterpret_cast<uint2*>(p)[1] = z;
        reinterpret_cast<uint2*>(p)[2] = z;
    }
    for (int idx = tid; idx < 128 * 32; idx += ETHREADS) {
        int n = idx >> 5, ck = idx & 31;
        float4 v = *reinterpret_cast<const float4*>(w2 + (size_t)n * D + ck * 4);
        uint2 u; u.x = pack_half2(v.x, v.y); u.y = pack_half2(v.z, v.w);
        *reinterpret_cast<uint2*>(dyn + OFF_W2N + n * 272 + ck * 8) = u;
    }
    if (tid < 128) {
        reinterpret_cast<float*>(dyn + OFF_B1E)[tid] = b1[tid];
        reinterpret_cast<float*>(dyn + OFF_B2E)[tid] = b2[tid];
    }
    const float* b1s = reinterpret_cast<const float*>(dyn + OFF_B1E);
    const float* b2s = reinterpret_cast<const float*>(dyn + OFF_B2E);

    int ntiles = (E + 127) >> 7;
    uint32_t atoff[2] = {OFF_AT0, OFF_AT1};

    if ((int)blockIdx.x < ntiles)
        stage_tile(dyn, atoff[0], 0, attr, eidx, elen, (int)blockIdx.x << 7, E, tid);
    __syncthreads();

    int b = 0;
    for (int t = blockIdx.x; t < ntiles; t += gridDim.x, b ^= 1) {
        int e0 = t << 7;
        const int* srcs = reinterpret_cast<const int*>(dyn + OFF_SRCE + b * 512);
        const int* dsts = reinterpret_cast<const int*>(dyn + OFF_DSTE + b * 512);
        const float* cs = reinterpret_cast<const float*>(dyn + OFF_CSE + b * 512);

        // prefetch xf[src] gather for this tile's epilogue — meta is already
        // staged (double buffer), latency hides under GEMM1+GEMM2
        float4 xf_pref[4];
        {
            int row = tid >> 3, q = tid & 7;
            if (e0 + row < E) {
                const float4* xp = reinterpret_cast<const float4*>(
                    g_xf + (size_t)srcs[row] * D + q * 16);
#pragma unroll
                for (int i = 0; i < 4; i++) xf_pref[i] = xp[i];
            } else {
#pragma unroll
                for (int i = 0; i < 4; i++) xf_pref[i] = make_float4(0.f, 0.f, 0.f, 0.f);
            }
        }

        float acc[4][4];
#pragma unroll
        for (int nt = 0; nt < 4; nt++)
#pragma unroll
            for (int i = 0; i < 4; i++) acc[nt][i] = 0.f;

        // GEMM1: C1 = attr @ W1^T  (K = 112)
#pragma unroll
        for (int ks = 0; ks < 7; ks++) {
            int k0h = ks * 16;
            uint32_t af[4], bf[2][4];
            LDSM_X4(af, sb + atoff[b] +
                (wm + (lane & 15)) * 240 +
                (k0h + ((lane >> 4) << 3)) * 2);
#pragma unroll
            for (int p = 0; p < 2; p++)
                LDSM_X4(bf[p], sb + OFF_W1N +
                    (wn + p * 16 + ((lane >> 4) << 3) + (lane & 7)) * 240 +
                    (k0h + (((lane >> 3) & 1) << 3)) * 2);
#pragma unroll
            for (int nt = 0; nt < 4; nt++)
                mma_f16(acc[nt], af, &bf[nt >> 1][(nt & 1) * 2], acc[nt]);
        }

        // H = fp16(ssp(C1 + b1)) -> HBWF
        {
            int row = wm + qr;
#pragma unroll
            for (int nt = 0; nt < 4; nt++) {
                int col = wn + nt * 8 + qc * 2;
                float bb0 = b1s[col], bb1 = b1s[col + 1];
                *reinterpret_cast<uint32_t*>(dyn + OFF_HBWF + row * 272 + col * 2) =
                    pack_half2(ssp_f(acc[nt][0] + bb0), ssp_f(acc[nt][1] + bb1));
                *reinterpret_cast<uint32_t*>(dyn + OFF_HBWF + (row + 8) * 272 + col * 2) =
                    pack_half2(ssp_f(acc[nt][2] + bb0), ssp_f(acc[nt][3] + bb1));
            }
        }
        __syncthreads();

        // stage NEXT tile into the other buffer (overlaps GEMM2)
        if (t + (int)gridDim.x < ntiles)
            stage_tile(dyn, atoff[b ^ 1], b ^ 1, attr, eidx, elen,
                       (t + (int)gridDim.x) << 7, E, tid);

#pragma unroll
        for (int nt = 0; nt < 4; nt++)
#pragma unroll
            for (int i = 0; i < 4; i++) acc[nt][i] = 0.f;

        // GEMM2: C2 = H @ W2^T  (K = 128)
#pragma unroll
        for (int ks = 0; ks < 8; ks++) {
            int k0h = ks * 16;
            uint32_t af[4], bf[2][4];
            LDSM_X4(af, sb + OFF_HBWF +
                (wm + (lane & 15)) * 272 +
                (k0h + ((lane >> 4) << 3)) * 2);
#pragma unroll
            for (int p = 0; p < 2; p++)
                LDSM_X4(bf[p], sb + OFF_W2N +
                    (wn + p * 16 + ((lane >> 4) << 3) + (lane & 7)) * 272 +
                    (k0h + (((lane >> 3) & 1) << 3)) * 2);
#pragma unroll
            for (int nt = 0; nt < 4; nt++)
                mma_f16(acc[nt], af, &bf[nt >> 1][(nt & 1) * 2], acc[nt]);
        }
        __syncthreads();   // all H reads done (and next-tile staging complete)

        // Wf = (C2 + b2) * C -> fp32 over HBWF
        {
            float* wf = reinterpret_cast<float*>(dyn + OFF_HBWF);
            int row = wm + qr;
            float c0 = cs[row], c1 = cs[row + 8];
#pragma unroll
            for (int nt = 0; nt < 4; nt++) {
                int col = wn + nt * 8 + qc * 2;
                float bb0 = b2s[col], bb1 = b2s[col + 1];
                float2 lo, hi;
                lo.x = (acc[nt][0] + bb0) * c0;
                lo.y = (acc[nt][1] + bb1) * c0;
                hi.x = (acc[nt][2] + bb0) * c1;
                hi.y = (acc[nt][3] + bb1) * c1;
                *reinterpret_cast<float2*>(wf + row * 132 + col) = lo;
                *reinterpret_cast<float2*>(wf + (row + 8) * 132 + col) = hi;
            }
        }
        __syncthreads();

        // epilogue: m_ij = xf_pref * Wf; red-add into m_i[dst]
        {
            const float* wfb = reinterpret_cast<const float*>(dyn + OFF_HBWF);
            int row = tid >> 3, q = tid & 7;
            int e = e0 + row;
            if (e < E) {
                int dst = dsts[row];
                float* mp = g_mi + (size_t)dst * D + q * 16;
                const float* wf = wfb + row * 132 + q * 16;
#pragma unroll
                for (int i = 0; i < 4; i++) {
                    float4 w = *reinterpret_cast<const float4*>(wf + i * 4);
                    float4 x = xf_pref[i];
                    float rx = w.x * x.x, ry = w.y * x.y;
                    float rz = w.z * x.z, rw = w.w * x.w;
                    asm volatile("red.global.add.v4.f32 [%0], {%1,%2,%3,%4};"
                                 :: "l"(mp + i * 4), "f"(rx), "f"(ry),
                                    "f"(rz), "f"(rw) : "memory");
                }
            }
        }
        __syncthreads();   // epilogue done before next iter's H store
    }
}

// ---------------- fused node kernel: update + next-layer xf (1024 threads) ----------------
#define NO_L2N  0        // lin2   [n][k] f16, stride 272
#define NO_LAN  34816    // lin_w cols 0:128
#define NO_LBN  69632    // lin_w cols 128:256
#define NO_L1N  104448   // lin1 (next layer)
#define NO_HF32 139264   // float[64][132]
#define NO_H16  173056   // half, 64 rows stride 272
#define NO_M16  190464   // half, 64 rows stride 272
#define NO_B2   207872
#define NO_BL   208384
#define NODE_SMEM 208896
#define NTHREADS 1024

__global__ __launch_bounds__(NTHREADS, 1)
void node_kernel(const float* __restrict__ lin2w,
                 const float* __restrict__ lin2b,
                 const float* __restrict__ linw,
                 const float* __restrict__ linb,
                 const float* __restrict__ lin1n,
                 int N, float* __restrict__ dout, int to_dout, int do_xf) {
    char* dyn = dynsmem;
    uint32_t sb = smem_u32(dyn);
    int tid = threadIdx.x, lane = tid & 31, wid = tid >> 5;   // 32 warps
    int qr = lane >> 2, qc = lane & 3;
    int wm = (wid & 3) * 16;   // 4 row groups x 16 rows
    int wn = (wid >> 2) * 16;  // 8 col groups x 16 cols

    float* outp = to_dout ? dout : g_h;

    for (int idx = tid; idx < 128 * 32; idx += NTHREADS) {
        int n = idx >> 5, ck = idx & 31;
        float4 v = *reinterpret_cast<const float4*>(lin2w + n * D + ck * 4);
        uint2 u; u.x = pack_half2(v.x, v.y); u.y = pack_half2(v.z, v.w);
        *reinterpret_cast<uint2*>(dyn + NO_L2N + n * 272 + ck * 8) = u;
    }
    for (int idx = tid; idx < 128 * 64; idx += NTHREADS) {
        int d_ = idx >> 6, c4 = idx & 63;
        float4 v = *reinterpret_cast<const float4*>(linw + d_ * 2 * D + c4 * 4);
        uint2 u; u.x = pack_half2(v.x, v.y); u.y = pack_half2(v.z, v.w);
        if (c4 < 32)
            *reinterpret_cast<uint2*>(dyn + NO_LAN + d_ * 272 + c4 * 8) = u;
        else
            *reinterpret_cast<uint2*>(dyn + NO_LBN + d_ * 272 + (c4 - 32) * 8) = u;
    }
    if (do_xf) {
        for (int idx = tid; idx < 128 * 32; idx += NTHREADS) {
            int n = idx >> 5, ck = idx & 31;
            float4 v = *reinterpret_cast<const float4*>(lin1n + n * D + ck * 4);
            uint2 u; u.x = pack_half2(v.x, v.y); u.y = pack_half2(v.z, v.w);
            *reinterpret_cast<uint2*>(dyn + NO_L1N + n * 272 + ck * 8) = u;
        }
    }
    if (tid < 128) {
        reinterpret_cast<float*>(dyn + NO_B2)[tid] = lin2b[tid];
        reinterpret_cast<float*>(dyn + NO_BL)[tid] = linb[tid];
    }
    const float* b2s = reinterpret_cast<const float*>(dyn + NO_B2);
    const float* bls = reinterpret_cast<const float*>(dyn + NO_BL);
    float* hf = reinterpret_cast<float*>(dyn + NO_HF32);

    int ntiles = (N + 63) >> 6;
    for (int t = blockIdx.x; t < ntiles; t += gridDim.x) {
        int r0 = t << 6;
        __syncthreads();

        for (int idx = tid; idx < 64 * 32; idx += NTHREADS) {
            int r = idx >> 5, c4 = idx & 31;
            int gr = r0 + r;
            float4 hv = make_float4(0.f, 0.f, 0.f, 0.f);
            float4 mv = hv;
            if (gr < N) {
                hv = *reinterpret_cast<const float4*>(g_h + (size_t)gr * D + c4 * 4);
                mv = *reinterpret_cast<const float4*>(g_mi + (size_t)gr * D + c4 * 4);
                if (do_xf)
                    *reinterpret_cast<float4*>(g_mi + (size_t)gr * D + c4 * 4) =
                        make_float4(0.f, 0.f, 0.f, 0.f);
            }
            *reinterpret_cast<float4*>(hf + r * 132 + c4 * 4) = hv;
            uint2 uh; uh.x = pack_half2(hv.x, hv.y); uh.y = pack_half2(hv.z, hv.w);
            *reinterpret_cast<uint2*>(dyn + NO_H16 + r * 272 + c4 * 8) = uh;
            uint2 um; um.x = pack_half2(mv.x, mv.y); um.y = pack_half2(mv.z, mv.w);
            *reinterpret_cast<uint2*>(dyn + NO_M16 + r * 272 + c4 * 8) = um;
        }
        __syncthreads();

        // GEMM m: Cm = m_i @ lin2^T
        float accm[2][4];
#pragma unroll
        for (int nt = 0; nt < 2; nt++)
#pragma unroll
            for (int i = 0; i < 4; i++) accm[nt][i] = 0.f;
#pragma unroll
        for (int ks = 0; ks < 8; ks++) {
            int k0h = ks * 16;
            uint32_t af[4], bf[4];
            LDSM_X4(af, sb + NO_M16 + (wm + (lane & 15)) * 272 +
                        (k0h + ((lane >> 4) << 3)) * 2);
            LDSM_X4(bf, sb + NO_L2N +
                (wn + ((lane >> 4) << 3) + (lane & 7)) * 272 +
                (k0h + (((lane >> 3) & 1) << 3)) * 2);
#pragma unroll
            for (int nt = 0; nt < 2; nt++)
                mma_f16(accm[nt], af, &bf[nt * 2], accm[nt]);
        }
        uint32_t mlo[2], mhi[2];
        int rowa = wm + qr;
#pragma unroll
        for (int nt = 0; nt < 2; nt++) {
            int col = wn + nt * 8 + qc * 2;
            float bb0 = b2s[col], bb1 = b2s[col + 1];
            mlo[nt] = pack_half2(ssp_f(accm[nt][0] + bb0), ssp_f(accm[nt][1] + bb1));
            mhi[nt] = pack_half2(ssp_f(accm[nt][2] + bb0), ssp_f(accm[nt][3] + bb1));
        }
        __syncthreads();   // all m_i reads done
#pragma unroll
        for (int nt = 0; nt < 2; nt++) {
            int col = wn + nt * 8 + qc * 2;
            *reinterpret_cast<uint32_t*>(dyn + NO_M16 + rowa * 272 + col * 2) = mlo[nt];
            *reinterpret_cast<uint32_t*>(dyn + NO_M16 + (rowa + 8) * 272 + col * 2) = mhi[nt];
        }
        __syncthreads();

        // GEMM out: acco = h@lwA + m@lwB
        float acco[2][4];
#pragma unroll
        for (int nt = 0; nt < 2; nt++)
#pragma unroll
            for (int i = 0; i < 4; i++) acco[nt][i] = 0.f;
#pragma unroll
        for (int ks = 0; ks < 8; ks++) {
            int k0h = ks * 16;
            uint32_t afh[4], afm[4], bfa[4], bfb[4];
            LDSM_X4(afh, sb + NO_H16 + (wm + (lane & 15)) * 272 +
                         (k0h + ((lane >> 4) << 3)) * 2);
            LDSM_X4(afm, sb + NO_M16 + (wm + (lane & 15)) * 272 +
                         (k0h + ((lane >> 4) << 3)) * 2);
            {
                uint32_t roff = (wn + ((lane >> 4) << 3) + (lane & 7)) * 272 +
                                (k0h + (((lane >> 3) & 1) << 3)) * 2;
                LDSM_X4(bfa, sb + NO_LAN + roff);
                LDSM_X4(bfb, sb + NO_LBN + roff);
            }
#pragma unroll
            for (int nt = 0; nt < 2; nt++) {
                mma_f16(acco[nt], afh, &bfa[nt * 2], acco[nt]);
                mma_f16(acco[nt], afm, &bfb[nt * 2], acco[nt]);
            }
        }
        float2 olo[2], ohi[2];
        int gr0 = r0 + rowa, gr1 = gr0 + 8;
#pragma unroll
        for (int nt = 0; nt < 2; nt++) {
            int col = wn + nt * 8 + qc * 2;
            float bb0 = bls[col], bb1 = bls[col + 1];
            float2 h0 = *reinterpret_cast<const float2*>(hf + rowa * 132 + col);
            float2 h1 = *reinterpret_cast<const float2*>(hf + (rowa + 8) * 132 + col);
            olo[nt].x = h0.x + acco[nt][0] + bb0;
            olo[nt].y = h0.y + acco[nt][1] + bb1;
            ohi[nt].x = h1.x + acco[nt][2] + bb0;
            ohi[nt].y = h1.y + acco[nt][3] + bb1;
            if (gr0 < N)
                *reinterpret_cast<float2*>(outp + (size_t)gr0 * D + col) = olo[nt];
            if (gr1 < N)
                *reinterpret_cast<float2*>(outp + (size_t)gr1 * D + col) = ohi[nt];
        }

        if (do_xf) {
            __syncthreads();   // H16 GEMM reads done before overwrite
#pragma unroll
            for (int nt = 0; nt < 2; nt++) {
                int col = wn + nt * 8 + qc * 2;
                *reinterpret_cast<uint32_t*>(dyn + NO_H16 + rowa * 272 + col * 2) =
                    pack_half2(olo[nt].x, olo[nt].y);
                *reinterpret_cast<uint32_t*>(dyn + NO_H16 + (rowa + 8) * 272 + col * 2) =
                    pack_half2(ohi[nt].x, ohi[nt].y);
            }
            __syncthreads();

            // GEMM xf: accx = h_new @ lin1(next)^T
            float accx[2][4];
#pragma unroll
            for (int nt = 0; nt < 2; nt++)
#pragma unroll
                for (int i = 0; i < 4; i++) accx[nt][i] = 0.f;
#pragma unroll
            for (int ks = 0; ks < 8; ks++) {
                int k0h = ks * 16;
                uint32_t af[4], bf[4];
                LDSM_X4(af, sb + NO_H16 + (wm + (lane & 15)) * 272 +
                            (k0h + ((lane >> 4) << 3)) * 2);
                LDSM_X4(bf, sb + NO_L1N +
                    (wn + ((lane >> 4) << 3) + (lane & 7)) * 272 +
                    (k0h + (((lane >> 3) & 1) << 3)) * 2);
#pragma unroll
                for (int nt = 0; nt < 2; nt++)
                    mma_f16(accx[nt], af, &bf[nt * 2], accx[nt]);
            }
#pragma unroll
            for (int nt = 0; nt < 2; nt++) {
                int col = wn + nt * 8 + qc * 2;
                float2 lo, hi;
                lo.x = accx[nt][0]; lo.y = accx[nt][1];
                hi.x = accx[nt][2]; hi.y = accx[nt][3];
                if (gr0 < N)
                    *reinterpret_cast<float2*>(g_xf + (size_t)gr0 * D + col) = lo;
                if (gr1 < N)
                    *reinterpret_cast<float2*>(g_xf + (size_t)gr1 * D + col) = hi;
            }
        }
    }
}

// ---------------- launch ----------------
extern "C" void kernel_launch(void* const* d_in, const int* in_sizes, int n_in,
                              void* d_out, int out_size) {
    const float* z    = (const float*)d_in[0];
    const int*   eidx = (const int*)d_in[1];
    const float* elen = (const float*)d_in[2];
    const float* attr = (const float*)d_in[3];
    const float* embw = (const float*)d_in[4];
    const float* embb = (const float*)d_in[5];
    const float* w1   = (const float*)d_in[6];
    const float* b1   = (const float*)d_in[7];
    const float* w2   = (const float*)d_in[8];
    const float* b2   = (const float*)d_in[9];
    const float* l1w  = (const float*)d_in[10];
    const float* l2w  = (const float*)d_in[11];
    const float* l2b  = (const float*)d_in[12];
    const float* lw   = (const float*)d_in[13];
    const float* lb   = (const float*)d_in[14];

    int N = in_sizes[0] / ZDIM;
    int E = in_sizes[2];

    const int XF_SMEM = (D * D + 64 * D) * 4;

    cudaFuncSetAttribute(xf_kernel,   cudaFuncAttributeMaxDynamicSharedMemorySize, XF_SMEM);
    cudaFuncSetAttribute(edge_kernel, cudaFuncAttributeMaxDynamicSharedMemorySize, EDGE_SMEM);
    cudaFuncSetAttribute(node_kernel, cudaFuncAttributeMaxDynamicSharedMemorySize, NODE_SMEM);

    int nsm = 148;
    cudaDeviceGetAttribute(&nsm, cudaDevAttrMultiProcessorCount, 0);

    int etiles = (E + 127) >> 7;
    int xtiles = (N + 63) >> 6;
    int ntn    = (N + 63) >> 6;
    int gx = 2 * nsm < xtiles ? 2 * nsm : xtiles;
    int ge = nsm < etiles ? nsm : etiles;
    int gn = nsm < ntn ? nsm : ntn;

    embed_kernel<<<(N * D + 255) / 256, 256>>>(z, embw, embb, N);
    xf_kernel<<<gx, 256, XF_SMEM>>>(l1w, N);   // lin1[0] + zero m_i

    for (int l = 0; l < NLAYERS; l++) {
        edge_kernel<<<ge, ETHREADS, EDGE_SMEM>>>(attr, eidx, elen,
                                            w1 + (size_t)l * D * G, b1 + (size_t)l * D,
                                            w2 + (size_t)l * D * D, b2 + (size_t)l * D, E);
        int do_xf = (l < NLAYERS - 1);
        const float* lin1n = do_xf ? (l1w + (size_t)(l + 1) * D * D) : l1w;
        int to_dout = (l == NLAYERS - 1) ? 1 : 0;
        node_kernel<<<gn, NTHREADS, NODE_SMEM>>>(
            l2w + (size_t)l * D * D, l2b + (size_t)l * D,
            lw + (size_t)l * D * 2 * D, lb + (size_t)l * D,
            lin1n, N, (float*)d_out, to_dout, do_xf);
    }
}